// round 16
// baseline (speedup 1.0000x reference)
#include <cuda_runtime.h>

// EGNN layer, B=4, N=512, D=64, H=1.
// R16: R11 kernels (measured-best edge math) + PDL overlap: edge kernel
// launched with programmaticStreamSerialization, issues its prep-independent
// streaming loads (rij/dij/mask) BEFORE griddepcontrol.wait, then reads prep
// outputs (g_a/g_bb/g_C4/g_gh/P/Q). Hides prep (~3.5us) behind edge ramp/loads.
// R15 lesson: edge is latency-bound, not issue-bound — instruction shaving is neutral.

#define BB 4
#define NN 512
#define DD 64
#define NNODE (BB * NN)

#define GH_BLOCKS    128
#define PQ_BLOCKS    24
#define CONST_BLOCK  (GH_BLOCKS + PQ_BLOCKS)
#define NODES_PER_GH 16

__device__ float  g_a  [NNODE];          // dot(h_i, eW1[0:D]) + eb1
__device__ float  g_bb [NNODE];          // dot(h_j, eW1[D:2D])
__device__ float  g_gh [NNODE * 3 * DD]; // bhh + Whh @ h per node
__device__ float  g_P  [3 * DD];
__device__ float  g_Q  [3 * DD];
__device__ float4 g_C4 [3];              // packed edge-MLP scalars

__device__ __forceinline__ float tanh_ap(float x) {
    float y;
    asm("tanh.approx.f32 %0, %1;" : "=f"(y) : "f"(x));
    return y;
}
__device__ __forceinline__ float sigmoid_f(float x) {
    return fmaf(tanh_ap(0.5f * x), 0.5f, 0.5f);
}
__device__ __forceinline__ float silu_f(float x) {
    return x * sigmoid_f(x);
}

// ---------------------------------------------------------------------------
// Kernel 1: prep (153 blocks).
// ---------------------------------------------------------------------------
__global__ __launch_bounds__(256) void prep_kernel(
    const float* __restrict__ h,   const float* __restrict__ eW1,
    const float* __restrict__ eb1,
    const float* __restrict__ nW2, const float* __restrict__ nb2,
    const float* __restrict__ Wih, const float* __restrict__ bih,
    const float* __restrict__ Whh, const float* __restrict__ bhh,
    const float* __restrict__ eW2, const float* __restrict__ eb2,
    const float* __restrict__ eW3, const float* __restrict__ eb3,
    const float* __restrict__ pW1, const float* __restrict__ pb1,
    const float* __restrict__ pW2, const float* __restrict__ pb2,
    const float* __restrict__ nW1, const float* __restrict__ nb1)
{
    const int tid = threadIdx.x;
    const int bid = blockIdx.x;

    if (bid < GH_BLOCKS) {
        __shared__ float wsh[(3 * DD) * 32];    // 24 KB, XOR-swizzled
        __shared__ float hs[NODES_PER_GH * DD]; // 4 KB
        __shared__ float se1[2 * DD];

        const int node0 = bid * NODES_PER_GH;
        {
            const float4* h4 = (const float4*)(h + (size_t)node0 * DD);
            ((float4*)hs)[tid] = h4[tid];
            if (tid < 2 * DD) se1[tid] = eW1[tid];
            #pragma unroll
            for (int i = 0; i < 6; i++) {
                const int e4 = tid + i * 256;
                const int r  = e4 >> 3;
                const int k4 = (e4 & 7) * 4;
                const float4 v = *(const float4*)(Whh + (size_t)r * DD + k4);
                const int rx = r & 31;
                wsh[r * 32 + ((k4 + 0) ^ rx)] = v.x;
                wsh[r * 32 + ((k4 + 1) ^ rx)] = v.y;
                wsh[r * 32 + ((k4 + 2) ^ rx)] = v.z;
                wsh[r * 32 + ((k4 + 3) ^ rx)] = v.w;
            }
        }
        __syncthreads();

        float acc[NODES_PER_GH];
        if (tid < 3 * DD) {
            const int r  = tid;
            const int rx = r & 31;
            const float* wr = wsh + r * 32;
            #pragma unroll
            for (int n = 0; n < NODES_PER_GH; n++) acc[n] = 0.f;
            #pragma unroll 8
            for (int k = 0; k < 32; k++) {
                const float w = wr[k ^ rx];
                #pragma unroll
                for (int n = 0; n < NODES_PER_GH; n++)
                    acc[n] = fmaf(w, hs[n * DD + k], acc[n]);
            }
        } else {
            const int u     = tid - 3 * DD;
            const int dot   = u >> 1;
            const int n     = dot >> 1;
            const int which = dot & 1;
            const int k0    = (u & 1) * 32;
            float p = 0.f;
            const float* hv = hs + n * DD + k0;
            const float* wv = se1 + which * DD + k0;
            #pragma unroll 8
            for (int kk = 0; kk < 32; kk++)
                p = fmaf(hv[kk], wv[kk], p);
            p += __shfl_down_sync(0xffffffffu, p, 1);
            if ((u & 1) == 0) {
                if (which == 0) g_a [node0 + n] = p + eb1[0];
                else            g_bb[node0 + n] = p;
            }
        }
        __syncthreads();

        #pragma unroll
        for (int i = 0; i < 6; i++) {
            const int e4 = tid + i * 256;
            const int r  = e4 >> 3;
            const int k4 = (e4 & 7) * 4;
            const float4 v = *(const float4*)(Whh + (size_t)r * DD + 32 + k4);
            const int rx = r & 31;
            wsh[r * 32 + ((k4 + 0) ^ rx)] = v.x;
            wsh[r * 32 + ((k4 + 1) ^ rx)] = v.y;
            wsh[r * 32 + ((k4 + 2) ^ rx)] = v.z;
            wsh[r * 32 + ((k4 + 3) ^ rx)] = v.w;
        }
        __syncthreads();

        if (tid < 3 * DD) {
            const int r  = tid;
            const int rx = r & 31;
            const float* wr = wsh + r * 32;
            #pragma unroll 8
            for (int k = 0; k < 32; k++) {
                const float w = wr[k ^ rx];
                #pragma unroll
                for (int n = 0; n < NODES_PER_GH; n++)
                    acc[n] = fmaf(w, hs[n * DD + 32 + k], acc[n]);
            }
            const float bh = bhh[r];
            #pragma unroll
            for (int n = 0; n < NODES_PER_GH; n++)
                g_gh[(size_t)(node0 + n) * (3 * DD) + r] = acc[n] + bh;
        }
    } else if (bid < CONST_BLOCK) {
        const int warp = (bid - GH_BLOCKS) * 8 + (tid >> 5);
        const int lane = tid & 31;
        if (warp < 3 * DD) {
            const float* __restrict__ Wr = Wih + (size_t)warp * DD;
            const float w0 = Wr[lane], w1 = Wr[32 + lane];
            float p = fmaf(w1, nW2[32 + lane], w0 * nW2[lane]);
            float q = fmaf(w1, (float)NN * nb2[32 + lane],
                           w0 * ((float)NN * nb2[lane]));
            #pragma unroll
            for (int o = 16; o > 0; o >>= 1) {
                p += __shfl_down_sync(0xffffffffu, p, o);
                q += __shfl_down_sync(0xffffffffu, q, o);
            }
            if (lane == 0) {
                g_P[warp] = p;
                g_Q[warp] = q + bih[warp];
            }
        }
    } else {
        if (tid == 0) {
            g_C4[0] = make_float4(eW1[2 * DD], eW2[0], eb2[0], eW3[0]);
            g_C4[1] = make_float4(eb3[0], pW1[0], pb1[0], pW2[0]);
            g_C4[2] = make_float4(pb2[0], nW1[0], nb1[0], 0.f);
        }
    }
}

// ---------------------------------------------------------------------------
__device__ __forceinline__ void edge_eval(
    float s_pre, float mij,
    float4 c0, float4 c1, float4 c2,
    float& ph, float& v)
{
    const float u  = silu_f(fmaf(silu_f(s_pre), c0.y, c0.z));
    const float mu = fmaf(u, c0.w, c1.x) * mij;
    ph = fmaf(silu_f(fmaf(mu, c1.y, c1.z)), c1.w, c2.x);
    v  = silu_f(fmaf(mu, c2.y, c2.z));
}

// ---------------------------------------------------------------------------
// Kernel 2: edge + x_new + GRU gates (R11 shape).  Launched with PDL:
// prep-independent loads issued before griddepcontrol.wait.
// ---------------------------------------------------------------------------
__global__ __launch_bounds__(128) void edge_gru_kernel(
    const float* __restrict__ h,
    const float* __restrict__ x,
    const float* __restrict__ rij,
    const float* __restrict__ dij,
    const float* __restrict__ mask,
    float* __restrict__ out)
{
    const int node = blockIdx.x;
    const int b    = node / NN;
    const int tid  = threadIdx.x;

    __shared__ float red[4][4];
    __shared__ float sS;

    const float4* __restrict__ d4 = (const float4*)(dij + (size_t)node * NN);
    const float4* __restrict__ r4 = (const float4*)(rij + (size_t)node * NN * 3);
    const float4* __restrict__ k4 = (const float4*)(mask + b * NN);

    // ---- prep-independent loads: in flight during prep's execution ----
    const float  mi = mask[node];
    const float4 dv = d4[tid];
    const float4 kv = k4[tid];
    const float4 A  = r4[3 * tid + 0];
    const float4 Bv = r4[3 * tid + 1];
    const float4 Cv = r4[3 * tid + 2];

    // ---- wait for prep grid, then read its outputs ----
    asm volatile("griddepcontrol.wait;" ::: "memory");

    const float4 c0 = g_C4[0];
    const float4 c1 = g_C4[1];
    const float4 c2 = g_C4[2];
    const float aib = g_a[node];          // includes +eb1
    const float4 bv = ((const float4*)(g_bb + b * NN))[tid];

    float ph0, ph1, ph2, ph3, v0, v1, v2, v3;
    edge_eval(fmaf(dv.x, c0.x, aib + bv.x), mi * kv.x, c0, c1, c2, ph0, v0);
    edge_eval(fmaf(dv.y, c0.x, aib + bv.y), mi * kv.y, c0, c1, c2, ph1, v1);
    edge_eval(fmaf(dv.z, c0.x, aib + bv.z), mi * kv.z, c0, c1, c2, ph2, v2);
    edge_eval(fmaf(dv.w, c0.x, aib + bv.w), mi * kv.w, c0, c1, c2, ph3, v3);

    float S  = (v0 + v1) + (v2 + v3);
    float x0 = A.x * ph0;
    float x1 = A.y * ph0;
    float x2 = A.z * ph0;
    x0 = fmaf(A.w,  ph1, x0);
    x1 = fmaf(Bv.x, ph1, x1);
    x2 = fmaf(Bv.y, ph1, x2);
    x0 = fmaf(Bv.z, ph2, x0);
    x1 = fmaf(Bv.w, ph2, x1);
    x2 = fmaf(Cv.x, ph2, x2);
    x0 = fmaf(Cv.y, ph3, x0);
    x1 = fmaf(Cv.z, ph3, x1);
    x2 = fmaf(Cv.w, ph3, x2);

    #pragma unroll
    for (int o = 16; o > 0; o >>= 1) {
        x0 += __shfl_down_sync(0xffffffffu, x0, o);
        x1 += __shfl_down_sync(0xffffffffu, x1, o);
        x2 += __shfl_down_sync(0xffffffffu, x2, o);
        S  += __shfl_down_sync(0xffffffffu, S , o);
    }
    const int wid = tid >> 5;
    if ((tid & 31) == 0) {
        red[wid][0] = x0; red[wid][1] = x1; red[wid][2] = x2; red[wid][3] = S;
    }
    __syncthreads();
    if (tid == 0) {
        float r0 = (red[0][0] + red[1][0]) + (red[2][0] + red[3][0]);
        float r1 = (red[0][1] + red[1][1]) + (red[2][1] + red[3][1]);
        float r2 = (red[0][2] + red[1][2]) + (red[2][2] + red[3][2]);
        float rs = (red[0][3] + red[1][3]) + (red[2][3] + red[3][3]);
        sS = rs;
        float* xo = out + (size_t)NNODE * DD + (size_t)node * 3;
        xo[0] = x[node * 3 + 0] + r0;
        xo[1] = x[node * 3 + 1] + r1;
        xo[2] = x[node * 3 + 2] + r2;
    }
    __syncthreads();

    // GRU gates: gh precomputed, gi rank-1 in S
    if (tid < DD) {
        const int d  = tid;
        const float Sv = sS;
        const float* gh = g_gh + (size_t)node * (3 * DD);
        const float ghr = gh[d];
        const float ghz = gh[DD + d];
        const float ghn = gh[2 * DD + d];
        const float gir = fmaf(Sv, g_P[d],          g_Q[d]);
        const float giz = fmaf(Sv, g_P[DD + d],     g_Q[DD + d]);
        const float gin = fmaf(Sv, g_P[2 * DD + d], g_Q[2 * DD + d]);
        const float r = sigmoid_f(gir + ghr);
        const float z = sigmoid_f(giz + ghz);
        const float n = tanh_ap(fmaf(r, ghn, gin));
        const float hv = h[node * DD + d];
        const float hnew = (1.0f - z) * n + z * hv;
        out[node * DD + d] = hnew * mi;
    }
}

// ---------------------------------------------------------------------------
extern "C" void kernel_launch(void* const* d_in, const int* in_sizes, int n_in,
                              void* d_out, int out_size) {
    const float* h    = (const float*)d_in[0];
    const float* x    = (const float*)d_in[1];
    const float* rij  = (const float*)d_in[2];
    const float* dij  = (const float*)d_in[3];
    const float* mask = (const float*)d_in[4];
    const float* eW1  = (const float*)d_in[5];
    const float* eb1  = (const float*)d_in[6];
    const float* eW2  = (const float*)d_in[7];
    const float* eb2  = (const float*)d_in[8];
    const float* eW3  = (const float*)d_in[9];
    const float* eb3  = (const float*)d_in[10];
    const float* pW1  = (const float*)d_in[11];
    const float* pb1  = (const float*)d_in[12];
    const float* pW2  = (const float*)d_in[13];
    const float* pb2  = (const float*)d_in[14];
    const float* nW1  = (const float*)d_in[15];
    const float* nb1  = (const float*)d_in[16];
    const float* nW2  = (const float*)d_in[17];
    const float* nb2  = (const float*)d_in[18];
    const float* Wih  = (const float*)d_in[19];
    const float* bih  = (const float*)d_in[20];
    const float* Whh  = (const float*)d_in[21];
    const float* bhh  = (const float*)d_in[22];
    float* out = (float*)d_out;

    prep_kernel<<<CONST_BLOCK + 1, 256>>>(
        h, eW1, eb1, nW2, nb2, Wih, bih, Whh, bhh,
        eW2, eb2, eW3, eb3, pW1, pb1, pW2, pb2, nW1, nb1);

    // PDL launch of the edge kernel: overlap its ramp + independent loads
    // with prep's execution.
    cudaLaunchConfig_t cfg = {};
    cfg.gridDim  = dim3(NNODE, 1, 1);
    cfg.blockDim = dim3(128, 1, 1);
    cfg.dynamicSmemBytes = 0;
    cfg.stream = 0;
    cudaLaunchAttribute attrs[1];
    attrs[0].id = cudaLaunchAttributeProgrammaticStreamSerialization;
    attrs[0].val.programmaticStreamSerializationAllowed = 1;
    cfg.attrs = attrs;
    cfg.numAttrs = 1;

    cudaError_t err = cudaLaunchKernelEx(&cfg, edge_gru_kernel,
                                         h, x, rij, dij, mask, out);
    if (err != cudaSuccess) {
        // fallback: classic serialized launch (griddepcontrol.wait is a no-op
        // when the kernel is not launched as a PDL secondary)
        edge_gru_kernel<<<NNODE, 128>>>(h, x, rij, dij, mask, out);
    }
}

// round 17
// speedup vs baseline: 1.0151x; 1.0151x over previous
#include <cuda_runtime.h>

// EGNN layer, B=4, N=512, D=64, H=1.
// R17: plain launches (PDL regressed R16). Edge kernel = R11 exactly (best
// measured 8.3us). Prep restructured: 256 gh blocks x 8 nodes, single-phase
// 49KB dynamic-smem Whh tile (one load, one barrier), 512-FMA chains.

#define BB 4
#define NN 512
#define DD 64
#define NNODE (BB * NN)

#define NODES_PER_GH 8
#define GH_BLOCKS    (NNODE / NODES_PER_GH)   // 256
#define PQ_BLOCKS    24
#define CONST_BLOCK  (GH_BLOCKS + PQ_BLOCKS)  // 280

// dynamic smem layout for gh blocks (floats):
//   wsh [192*64] XOR-swizzled Whh     (49152 B)
//   hs  [8*64]                        (2048 B)
//   se1 [128]                         (512 B)
#define SMEM_FLOATS ((3 * DD) * DD + NODES_PER_GH * DD + 2 * DD)
#define SMEM_BYTES  (SMEM_FLOATS * 4)

__device__ float  g_a  [NNODE];          // dot(h_i, eW1[0:D]) + eb1
__device__ float  g_bb [NNODE];          // dot(h_j, eW1[D:2D])
__device__ float  g_gh [NNODE * 3 * DD]; // bhh + Whh @ h per node
__device__ float  g_P  [3 * DD];
__device__ float  g_Q  [3 * DD];
__device__ float4 g_C4 [3];              // packed edge-MLP scalars

__device__ __forceinline__ float tanh_ap(float x) {
    float y;
    asm("tanh.approx.f32 %0, %1;" : "=f"(y) : "f"(x));
    return y;
}
__device__ __forceinline__ float sigmoid_f(float x) {
    return fmaf(tanh_ap(0.5f * x), 0.5f, 0.5f);
}
__device__ __forceinline__ float silu_f(float x) {
    return x * sigmoid_f(x);
}

// ---------------------------------------------------------------------------
// Kernel 1: prep (280 blocks, 256 threads).
//   [0,256):  gh GEMM for 8 nodes (single smem phase) + projections a/b
//   [256,280): P/Q (warp per output row)
//   block 279 thread 255: pack g_C4
// ---------------------------------------------------------------------------
__global__ __launch_bounds__(256) void prep_kernel(
    const float* __restrict__ h,   const float* __restrict__ eW1,
    const float* __restrict__ eb1,
    const float* __restrict__ nW2, const float* __restrict__ nb2,
    const float* __restrict__ Wih, const float* __restrict__ bih,
    const float* __restrict__ Whh, const float* __restrict__ bhh,
    const float* __restrict__ eW2, const float* __restrict__ eb2,
    const float* __restrict__ eW3, const float* __restrict__ eb3,
    const float* __restrict__ pW1, const float* __restrict__ pb1,
    const float* __restrict__ pW2, const float* __restrict__ pb2,
    const float* __restrict__ nW1, const float* __restrict__ nb1)
{
    const int tid = threadIdx.x;
    const int bid = blockIdx.x;

    if (bid < GH_BLOCKS) {
        extern __shared__ float sm[];
        float* wsh = sm;                              // 192*64, swizzled
        float* hs  = sm + (3 * DD) * DD;              // 8*64
        float* se1 = hs + NODES_PER_GH * DD;          // 128

        const int node0 = bid * NODES_PER_GH;

        // ---- stage: Whh (192x64, XOR swizzle within 64-col row), hs, se1 ----
        #pragma unroll
        for (int i = 0; i < 12; i++) {
            const int e4 = tid + i * 256;             // float4 idx < 3072
            const int r  = e4 >> 4;                   // 0..191
            const int k4 = (e4 & 15) * 4;             // 0..60
            const float4 v = *(const float4*)(Whh + (size_t)r * DD + k4);
            const int rx = r & 31;
            wsh[r * DD + ((k4 + 0) ^ rx)] = v.x;
            wsh[r * DD + ((k4 + 1) ^ rx)] = v.y;
            wsh[r * DD + ((k4 + 2) ^ rx)] = v.z;
            wsh[r * DD + ((k4 + 3) ^ rx)] = v.w;
        }
        if (tid < NODES_PER_GH * DD / 4) {            // 128 float4
            const float4* h4 = (const float4*)(h + (size_t)node0 * DD);
            ((float4*)hs)[tid] = h4[tid];
        }
        if (tid < 2 * DD) se1[tid] = eW1[tid];
        __syncthreads();

        if (tid < 3 * DD) {
            // gh GEMM: row r for 8 nodes, 512 FMA
            const int r  = tid;
            const int rx = r & 31;
            const float* wr = wsh + r * DD;
            float acc[NODES_PER_GH];
            #pragma unroll
            for (int n = 0; n < NODES_PER_GH; n++) acc[n] = 0.f;
            #pragma unroll 8
            for (int k = 0; k < DD; k++) {
                const float w = wr[k ^ rx];
                #pragma unroll
                for (int n = 0; n < NODES_PER_GH; n++)
                    acc[n] = fmaf(w, hs[n * DD + k], acc[n]);
            }
            const float bh = bhh[r];
            #pragma unroll
            for (int n = 0; n < NODES_PER_GH; n++)
                g_gh[(size_t)(node0 + n) * (3 * DD) + r] = acc[n] + bh;
        } else {
            // projections: 64 threads, 16 dots (8 nodes x {a,b}), 4 thr/dot
            const int u     = tid - 3 * DD;           // 0..63
            const int dot   = u >> 2;                 // 0..15
            const int n     = dot >> 1;
            const int which = dot & 1;
            const int k0    = (u & 3) * 16;
            float p = 0.f;
            const float* hv = hs + n * DD + k0;
            const float* wv = se1 + which * DD + k0;
            #pragma unroll
            for (int kk = 0; kk < 16; kk++)
                p = fmaf(hv[kk], wv[kk], p);
            p += __shfl_down_sync(0xffffffffu, p, 2);
            p += __shfl_down_sync(0xffffffffu, p, 1);
            if ((u & 3) == 0) {
                if (which == 0) g_a [node0 + n] = p + eb1[0];
                else            g_bb[node0 + n] = p;
            }
        }
    } else {
        // P/Q: warp per output row r
        const int warp = (bid - GH_BLOCKS) * 8 + (tid >> 5);
        const int lane = tid & 31;
        if (warp < 3 * DD) {
            const float* __restrict__ Wr = Wih + (size_t)warp * DD;
            const float w0 = Wr[lane], w1 = Wr[32 + lane];
            float p = fmaf(w1, nW2[32 + lane], w0 * nW2[lane]);
            float q = fmaf(w1, (float)NN * nb2[32 + lane],
                           w0 * ((float)NN * nb2[lane]));
            #pragma unroll
            for (int o = 16; o > 0; o >>= 1) {
                p += __shfl_down_sync(0xffffffffu, p, o);
                q += __shfl_down_sync(0xffffffffu, q, o);
            }
            if (lane == 0) {
                g_P[warp] = p;
                g_Q[warp] = q + bih[warp];
            }
        }
        if (bid == CONST_BLOCK - 1 && tid == 255) {
            g_C4[0] = make_float4(eW1[2 * DD], eW2[0], eb2[0], eW3[0]);
            g_C4[1] = make_float4(eb3[0], pW1[0], pb1[0], pW2[0]);
            g_C4[2] = make_float4(pb2[0], nW1[0], nb1[0], 0.f);
        }
    }
}

// ---------------------------------------------------------------------------
__device__ __forceinline__ void edge_eval(
    float s_pre, float mij,
    float4 c0, float4 c1, float4 c2,
    float& ph, float& v)
{
    const float u  = silu_f(fmaf(silu_f(s_pre), c0.y, c0.z));
    const float mu = fmaf(u, c0.w, c1.x) * mij;
    ph = fmaf(silu_f(fmaf(mu, c1.y, c1.z)), c1.w, c2.x);
    v  = silu_f(fmaf(mu, c2.y, c2.z));
}

// ---------------------------------------------------------------------------
// Kernel 2: edge + x_new + GRU gates (R11 shape, unchanged — best measured).
// ---------------------------------------------------------------------------
__global__ __launch_bounds__(128) void edge_gru_kernel(
    const float* __restrict__ h,
    const float* __restrict__ x,
    const float* __restrict__ rij,
    const float* __restrict__ dij,
    const float* __restrict__ mask,
    float* __restrict__ out)
{
    const int node = blockIdx.x;
    const int b    = node / NN;
    const int tid  = threadIdx.x;

    __shared__ float red[4][4];
    __shared__ float sS;

    const float4 c0 = g_C4[0];
    const float4 c1 = g_C4[1];
    const float4 c2 = g_C4[2];

    const float mi  = mask[node];
    const float aib = g_a[node];          // includes +eb1

    const float4* __restrict__ d4 = (const float4*)(dij + (size_t)node * NN);
    const float4* __restrict__ r4 = (const float4*)(rij + (size_t)node * NN * 3);
    const float4* __restrict__ b4 = (const float4*)(g_bb + b * NN);
    const float4* __restrict__ k4 = (const float4*)(mask + b * NN);

    const float4 dv = d4[tid];
    const float4 bv = b4[tid];
    const float4 kv = k4[tid];
    const float4 A  = r4[3 * tid + 0];
    const float4 Bv = r4[3 * tid + 1];
    const float4 Cv = r4[3 * tid + 2];

    float ph0, ph1, ph2, ph3, v0, v1, v2, v3;
    edge_eval(fmaf(dv.x, c0.x, aib + bv.x), mi * kv.x, c0, c1, c2, ph0, v0);
    edge_eval(fmaf(dv.y, c0.x, aib + bv.y), mi * kv.y, c0, c1, c2, ph1, v1);
    edge_eval(fmaf(dv.z, c0.x, aib + bv.z), mi * kv.z, c0, c1, c2, ph2, v2);
    edge_eval(fmaf(dv.w, c0.x, aib + bv.w), mi * kv.w, c0, c1, c2, ph3, v3);

    float S  = (v0 + v1) + (v2 + v3);
    float x0 = A.x * ph0;
    float x1 = A.y * ph0;
    float x2 = A.z * ph0;
    x0 = fmaf(A.w,  ph1, x0);
    x1 = fmaf(Bv.x, ph1, x1);
    x2 = fmaf(Bv.y, ph1, x2);
    x0 = fmaf(Bv.z, ph2, x0);
    x1 = fmaf(Bv.w, ph2, x1);
    x2 = fmaf(Cv.x, ph2, x2);
    x0 = fmaf(Cv.y, ph3, x0);
    x1 = fmaf(Cv.z, ph3, x1);
    x2 = fmaf(Cv.w, ph3, x2);

    #pragma unroll
    for (int o = 16; o > 0; o >>= 1) {
        x0 += __shfl_down_sync(0xffffffffu, x0, o);
        x1 += __shfl_down_sync(0xffffffffu, x1, o);
        x2 += __shfl_down_sync(0xffffffffu, x2, o);
        S  += __shfl_down_sync(0xffffffffu, S , o);
    }
    const int wid = tid >> 5;
    if ((tid & 31) == 0) {
        red[wid][0] = x0; red[wid][1] = x1; red[wid][2] = x2; red[wid][3] = S;
    }
    __syncthreads();
    if (tid == 0) {
        float r0 = (red[0][0] + red[1][0]) + (red[2][0] + red[3][0]);
        float r1 = (red[0][1] + red[1][1]) + (red[2][1] + red[3][1]);
        float r2 = (red[0][2] + red[1][2]) + (red[2][2] + red[3][2]);
        float rs = (red[0][3] + red[1][3]) + (red[2][3] + red[3][3]);
        sS = rs;
        float* xo = out + (size_t)NNODE * DD + (size_t)node * 3;
        xo[0] = x[node * 3 + 0] + r0;
        xo[1] = x[node * 3 + 1] + r1;
        xo[2] = x[node * 3 + 2] + r2;
    }
    __syncthreads();

    // GRU gates: gh precomputed, gi rank-1 in S
    if (tid < DD) {
        const int d  = tid;
        const float Sv = sS;
        const float* gh = g_gh + (size_t)node * (3 * DD);
        const float ghr = gh[d];
        const float ghz = gh[DD + d];
        const float ghn = gh[2 * DD + d];
        const float gir = fmaf(Sv, g_P[d],          g_Q[d]);
        const float giz = fmaf(Sv, g_P[DD + d],     g_Q[DD + d]);
        const float gin = fmaf(Sv, g_P[2 * DD + d], g_Q[2 * DD + d]);
        const float r = sigmoid_f(gir + ghr);
        const float z = sigmoid_f(giz + ghz);
        const float n = tanh_ap(fmaf(r, ghn, gin));
        const float hv = h[node * DD + d];
        const float hnew = (1.0f - z) * n + z * hv;
        out[node * DD + d] = hnew * mi;
    }
}

// ---------------------------------------------------------------------------
extern "C" void kernel_launch(void* const* d_in, const int* in_sizes, int n_in,
                              void* d_out, int out_size) {
    const float* h    = (const float*)d_in[0];
    const float* x    = (const float*)d_in[1];
    const float* rij  = (const float*)d_in[2];
    const float* dij  = (const float*)d_in[3];
    const float* mask = (const float*)d_in[4];
    const float* eW1  = (const float*)d_in[5];
    const float* eb1  = (const float*)d_in[6];
    const float* eW2  = (const float*)d_in[7];
    const float* eb2  = (const float*)d_in[8];
    const float* eW3  = (const float*)d_in[9];
    const float* eb3  = (const float*)d_in[10];
    const float* pW1  = (const float*)d_in[11];
    const float* pb1  = (const float*)d_in[12];
    const float* pW2  = (const float*)d_in[13];
    const float* pb2  = (const float*)d_in[14];
    const float* nW1  = (const float*)d_in[15];
    const float* nb1  = (const float*)d_in[16];
    const float* nW2  = (const float*)d_in[17];
    const float* nb2  = (const float*)d_in[18];
    const float* Wih  = (const float*)d_in[19];
    const float* bih  = (const float*)d_in[20];
    const float* Whh  = (const float*)d_in[21];
    const float* bhh  = (const float*)d_in[22];
    float* out = (float*)d_out;

    static bool attr_done = false;
    if (!attr_done) {
        cudaFuncSetAttribute(prep_kernel,
                             cudaFuncAttributeMaxDynamicSharedMemorySize,
                             SMEM_BYTES);
        attr_done = true;
    }

    prep_kernel<<<CONST_BLOCK, 256, SMEM_BYTES>>>(
        h, eW1, eb1, nW2, nb2, Wih, bih, Whh, bhh,
        eW2, eb2, eW3, eb3, pW1, pb1, pW2, pb2, nW1, nb1);
    edge_gru_kernel<<<NNODE, 128>>>(h, x, rij, dij, mask, out);
}